// round 13
// baseline (speedup 1.0000x reference)
#include <cuda_runtime.h>
#include <cuda_bf16.h>
#include <cstdint>

// MaskSupervisionLoss on GB300 (sm_103a) — persistent single-wave kernel,
// per-warp barrier-free cp.async pipelines, compile-time tile count.
// Inputs: pred_attn f32 (32,8,256,256), gt_masks f32 (32,8,256,256), num_objects i32 (32)
// Output: scalar f32 loss.

#define NB      32
#define NSLOT   8
#define HW      65536
#define CTAB    16                 // CTAs per batch (16*32 = 512 CTAs, single wave)
#define TILE    128                // positions per tile
#define CNT     32                 // tiles per CTA (compile-time!)
#define STAGES  4
#define TPB     128
#define NV      66
#define EPSF    1e-6f

// canonical layout (per batch):
//  0 bg_inter, 1 bg_psum, 2 bg_gsum, 3..9 psum fg0-6, 10..16 gsum fg0-6,
//  17..65 inter[p][g] = 17 + 7p + g

__device__ float g_scratch[NB * CTAB * NV];
__device__ float g_batch[NB * 3];
__device__ int   g_cnt[NB];        // zero-init; self-resetting
__device__ int   g_cnt_all;        // zero-init; self-resetting

__device__ __forceinline__ void cp16(unsigned int dst_smem, const float* src) {
    asm volatile("cp.async.cg.shared.global [%0], [%1], 16;\n"
                 :: "r"(dst_smem), "l"(src));
}
__device__ __forceinline__ void cp_commit() {
    asm volatile("cp.async.commit_group;\n");
}
template <int N>
__device__ __forceinline__ void cp_wait() {
    asm volatile("cp.async.wait_group %0;\n" :: "n"(N));
}

// ---------------------------------------------------------------------------
__global__ __launch_bounds__(TPB, 5)
void k_fused(const float* __restrict__ pred, const float* __restrict__ gt,
             const int* __restrict__ nobj, float* __restrict__ out) {
    const int idx  = blockIdx.x;       // 0..15 within batch
    const int b    = blockIdx.y;
    const int tid  = threadIdx.x;
    const int wid  = tid >> 5;
    const int lane = tid & 31;

    // stage = 16 streams x 128 floats = 8KB ; 4 stages = 32KB
    __shared__ float buf[STAGES][16][TILE];
    __shared__ float sw[4][NV];
    __shared__ int   sflag;

    const float* __restrict__ bp = pred + (size_t)b * NSLOT * HW;
    const float* __restrict__ bg = gt   + (size_t)b * NSLOT * HW;

    // per-warp private pipeline: warp w loads exactly the 16 x 128B segments
    // its own lanes consume (positions 32w..32w+31). 4 cp16 per lane per tile.
    //   j-th op: o = j*32 + lane ; stream s = o>>3 ; 16B unit u = o&7
    const unsigned int smem0 = (unsigned int)__cvta_generic_to_shared(&buf[0][0][0]);
    const float* sp[4];
    unsigned int dstb[4];
#pragma unroll
    for (int j = 0; j < 4; j++) {
        const int o = j * 32 + lane;
        const int s = o >> 3;
        const int u = o & 7;
        const float* sb = (s < 8) ? (bp + s * HW) : (bg + (s - 8) * HW);
        sp[j]   = sb + (size_t)idx * (CNT * TILE) + wid * 32 + u * 4;
        dstb[j] = smem0 + (unsigned int)((s * TILE + wid * 32 + u * 4) * 4);
    }

    float acc[NV];
#pragma unroll
    for (int v = 0; v < NV; v++) acc[v] = 0.f;

    // ---- prologue: tiles 0..3 into stages 0..3
#pragma unroll
    for (int T = 0; T < 4; T++) {
        const unsigned int so = (unsigned int)(T * 16 * TILE * 4);
#pragma unroll
        for (int j = 0; j < 4; j++)
            cp16(dstb[j] + so, sp[j] + T * TILE);
        cp_commit();
    }
#pragma unroll
    for (int j = 0; j < 4; j++) sp[j] += 4 * TILE;   // now point at tile 4

    // ---- main loop: outer 8 x inner 4 ; stage == inner index (STAGES=4)
    for (int o = 0; o < 8; o++) {
        const bool pf = (o < 7);     // tiles 28..31 issue no loads
#pragma unroll
        for (int i = 0; i < 4; i++) {
            if (pf) {
                const unsigned int so = (unsigned int)(i * 16 * TILE * 4);
#pragma unroll
                for (int j = 0; j < 4; j++)
                    cp16(dstb[j] + so, sp[j] + i * TILE);
            }
            cp_commit();
            cp_wait<3>();

            const float* tb = &buf[i][0][0] + tid;
            // gt slots resident (8 regs), pred rows streamed one at a time
            float g[8];
#pragma unroll
            for (int s = 0; s < 8; s++) g[s] = tb[(8 + s) * TILE];
            acc[2] += g[0];
#pragma unroll
            for (int c = 0; c < 7; c++) acc[10 + c] += g[1 + c];

            float p = tb[0];
            acc[0] = fmaf(p, g[0], acc[0]);
            acc[1] += p;
#pragma unroll
            for (int r = 0; r < 7; r++) {
                p = tb[(1 + r) * TILE];
                acc[3 + r] += p;
#pragma unroll
                for (int c = 0; c < 7; c++)
                    acc[17 + r * 7 + c] = fmaf(p, g[1 + c], acc[17 + r * 7 + c]);
            }
        }
        if (pf) {
#pragma unroll
            for (int j = 0; j < 4; j++) sp[j] += 4 * TILE;
        }
    }
    cp_wait<0>();

    // ---- block reduction: warp tree + 4-warp combine, publish canonical 66
#pragma unroll
    for (int v = 0; v < NV; v++) {
        float x = acc[v];
#pragma unroll
        for (int o = 16; o > 0; o >>= 1) x += __shfl_down_sync(0xffffffffu, x, o);
        if (lane == 0) sw[wid][v] = x;
    }
    __syncthreads();

    if (tid < NV) {
        g_scratch[(b * CTAB + idx) * NV + tid] =
            sw[0][tid] + sw[1][tid] + sw[2][tid] + sw[3][tid];
        __threadfence();
    }
    __syncthreads();

    if (tid == 0) sflag = (atomicAdd(&g_cnt[b], 1) == CTAB - 1);
    __syncthreads();
    if (!sflag) return;

    // ================= batch finisher (last CTA of this batch) ===============
    __shared__ float part[132];
    __shared__ float sm66[NV];
    __shared__ float dice[49];
    __shared__ float dpt[128];

    __threadfence();
    if (tid < 132) {
        const int v = tid >> 1, h = tid & 1;
        float s = 0.f;
#pragma unroll
        for (int c = 0; c < CTAB / 2; c++)
            s += __ldcg(&g_scratch[(b * CTAB + h * (CTAB / 2) + c) * NV + v]);
        part[tid] = s;
    }
    __syncthreads();
    if (tid < NV) sm66[tid] = part[2 * tid] + part[2 * tid + 1];
    __syncthreads();
    if (tid < 49) {
        const int p = tid / 7, g = tid % 7;
        dice[tid] = (2.f * sm66[17 + tid] + EPSF) / (sm66[3 + p] + sm66[10 + g] + EPSF);
    }
    __syncthreads();

    if (wid == 0) {
        int n = nobj[b];
        n = (n > 7) ? 7 : (n < 0 ? 0 : n);
#pragma unroll
        for (int k = 0; k < 4; k++) dpt[k * 32 + lane] = -1e30f;
        __syncwarp();
        if (lane == 0) dpt[0] = 0.f;
        __syncwarp();
        // layered bitmask DP: optimal assignment value == Hungarian optimum
#pragma unroll
        for (int L = 1; L <= 7; L++) {
            const int g = L - 1;
            if (g < n) {
#pragma unroll
                for (int k = 0; k < 4; k++) {
                    const int m = k * 32 + lane;
                    if (__popc(m) == L) {
                        float best = -1e30f;
#pragma unroll
                        for (int p = 0; p < 7; p++)
                            if (m & (1 << p))
                                best = fmaxf(best, dpt[m ^ (1 << p)] + dice[p * 7 + g]);
                        dpt[m] = best;
                    }
                }
            }
            __syncwarp();
        }
        float best = -1e30f;
        if (n > 0) {
#pragma unroll
            for (int k = 0; k < 4; k++) {
                const int m = k * 32 + lane;
                if (__popc(m) == n) best = fmaxf(best, dpt[m]);
            }
        }
#pragma unroll
        for (int o = 16; o > 0; o >>= 1)
            best = fmaxf(best, __shfl_xor_sync(0xffffffffu, best, o));
        if (lane == 0) {
            g_batch[b * 3 + 0] = (2.f * sm66[0] + EPSF) / (sm66[1] + sm66[2] + EPSF);
            g_batch[b * 3 + 1] = (float)n;
            g_batch[b * 3 + 2] = (n > 0) ? best : 0.f;
        }
    }
    __syncthreads();

    if (tid == 0) {
        g_cnt[b] = 0;                       // reset for next graph replay
        __threadfence();
        sflag = (atomicAdd(&g_cnt_all, 1) == NB - 1);
    }
    __syncthreads();
    if (!sflag) return;

    // ================= global finisher =================
    if (wid == 0) {
        __threadfence();
        const float bgd = __ldcg(&g_batch[lane * 3 + 0]);
        const float nn  = __ldcg(&g_batch[lane * 3 + 1]);
        const float sv  = __ldcg(&g_batch[lane * 3 + 2]);
        float bg  = 1.f - bgd;
        float tot = nn;
        float ss  = (nn > 0.f) ? sv : 0.f;
#pragma unroll
        for (int o = 16; o > 0; o >>= 1) {
            bg  += __shfl_xor_sync(0xffffffffu, bg,  o);
            tot += __shfl_xor_sync(0xffffffffu, tot, o);
            ss  += __shfl_xor_sync(0xffffffffu, ss,  o);
        }
        if (lane == 0) {
            const float fg = (tot > 0.f) ? (tot - ss) / tot : 0.f;
            out[0] = bg * (1.f / (float)NB) + fg;
            g_cnt_all = 0;                  // reset for next graph replay
        }
    }
}

// ---------------------------------------------------------------------------
extern "C" void kernel_launch(void* const* d_in, const int* in_sizes, int n_in,
                              void* d_out, int out_size) {
    const float* pred = (const float*)d_in[0];
    const float* gt   = (const float*)d_in[1];
    const int*   nobj = (const int*)d_in[2];
    float*       out  = (float*)d_out;

    dim3 grid(CTAB, NB);
    k_fused<<<grid, TPB>>>(pred, gt, nobj, out);
}